// round 11
// baseline (speedup 1.0000x reference)
#include <cuda_runtime.h>
#include <cuda_bf16.h>
#include <cstdint>

#define D 512
#define NDRUGS 4096
#define CAP 128
#define BM 128
#define BN 128
#define BK 64

// ---------------- device scratch (allocation-free) ----------------
__device__ __align__(16) __nv_bfloat16  g_Uh[NDRUGS * D];    // 4 MB (U = (z*d)@W, bf16)
__device__ __align__(16) __nv_bfloat16  g_Ah[NDRUGS * D];    // 4 MB (bf16 of z*d)
__device__ __align__(16) __nv_bfloat16  g_Bh[D * D];         // 512 KB (W^T bf16)
__device__ int  g_cnt[NDRUGS];                               // zero-init; restored each launch
__device__ __align__(16) int2 g_bkt[NDRUGS * CAP];           // 4 MB fixed-capacity buckets

// ---------------- helpers ----------------
__device__ __forceinline__ uint32_t smem_to_u32(const void* p) {
    uint32_t a;
    asm("{ .reg .u64 t; cvta.to.shared.u64 t, %1; cvt.u32.u64 %0, t; }" : "=r"(a) : "l"(p));
    return a;
}
#define SMEM_SWIZZLE_128B(o) ((o) ^ (((o) >> 3) & 0x70))

#define CP_ASYNC16(dst, src) \
    asm volatile("cp.async.cg.shared.global [%0], [%1], 16;" :: "r"(dst), "l"(src))
#define CP_COMMIT() asm volatile("cp.async.commit_group;" ::: "memory")
#define CP_WAIT(n)  asm volatile("cp.async.wait_group %0;" :: "n"(n) : "memory")

__device__ __forceinline__ void ldsm_x4(uint32_t& r0, uint32_t& r1, uint32_t& r2, uint32_t& r3,
                                        uint32_t addr) {
    asm volatile("ldmatrix.sync.aligned.m8n8.x4.shared.b16 {%0,%1,%2,%3}, [%4];"
                 : "=r"(r0), "=r"(r1), "=r"(r2), "=r"(r3) : "r"(addr));
}
__device__ __forceinline__ void mma_bf16(float* c, const uint32_t* a, uint32_t b0, uint32_t b1) {
    asm volatile("mma.sync.aligned.m16n8k16.row.col.f32.bf16.bf16.f32 "
                 "{%0,%1,%2,%3}, {%4,%5,%6,%7}, {%8,%9}, {%0,%1,%2,%3};"
                 : "+f"(c[0]), "+f"(c[1]), "+f"(c[2]), "+f"(c[3])
                 : "r"(a[0]), "r"(a[1]), "r"(a[2]), "r"(a[3]), "r"(b0), "r"(b1));
}

// GEMM SMEM: 2 stages x (Ah 16K | Bh 16K) = 64 KB
#define STAGE_BYTES 32768
#define AH_OFF 0
#define BH_OFF 16384
#define SM_GEMM (2 * STAGE_BYTES)

// ---------------------------------------------------------------------------
// Prep A: Ah = bf16(z[m,k] * d[k])
// ---------------------------------------------------------------------------
__global__ __launch_bounds__(256) void prep_a_kernel(
    const float* __restrict__ z, const float* __restrict__ ldiag, const int* __restrict__ idxp)
{
    const float* dp = ldiag + idxp[0] * D;
    int i = blockIdx.x * 256 + threadIdx.x;
    int k4 = (i & (D / 4 - 1)) << 2;
    float4 v = ((const float4*)z)[i];
    v.x *= dp[k4 + 0]; v.y *= dp[k4 + 1]; v.z *= dp[k4 + 2]; v.w *= dp[k4 + 3];

    __nv_bfloat162 h01 = __floats2bfloat162_rn(v.x, v.y);
    __nv_bfloat162 h23 = __floats2bfloat162_rn(v.z, v.w);
    uint2 hp; hp.x = *(uint32_t*)&h01; hp.y = *(uint32_t*)&h23;
    ((uint2*)g_Ah)[i] = hp;
}

// ---------------------------------------------------------------------------
// Prep W: Bh[n,k] = bf16(W[k,n])
// ---------------------------------------------------------------------------
__global__ __launch_bounds__(256) void prep_w_kernel(const float* __restrict__ W)
{
    __shared__ float t[32][33];
    int tx = threadIdx.x, ty = threadIdx.y;
    int x0 = blockIdx.x * 32, y0 = blockIdx.y * 32;
    #pragma unroll
    for (int r = 0; r < 4; r++)
        t[ty + r * 8][tx] = W[(y0 + ty + r * 8) * D + x0 + tx];
    __syncthreads();
    #pragma unroll
    for (int r = 0; r < 4; r++) {
        int n = x0 + ty + r * 8;
        int k = y0 + tx;
        g_Bh[n * D + k] = __float2bfloat16(t[tx][ty + r * 8]);
    }
}

// ---------------------------------------------------------------------------
// Scatter: bucket edges by row index (no hist, no scan)
// ---------------------------------------------------------------------------
__global__ __launch_bounds__(256) void scatter_kernel(const int* __restrict__ edges, int n_edges)
{
    int e = blockIdx.x * 256 + threadIdx.x;
    if (e < n_edges) {
        int r = edges[e];
        int c = edges[n_edges + e];
        int p = atomicAdd(&g_cnt[r], 1);
        if (p < CAP) g_bkt[r * CAP + p] = make_int2(c, e);
    }
}

// ---------------------------------------------------------------------------
// bf16 GEMM via mma.sync: Uh = bf16( Ah @ Wh )
// ---------------------------------------------------------------------------
__global__ __launch_bounds__(256, 1) void dedicom_mma_kernel()
{
    extern __shared__ char smem[];
    const int tid  = threadIdx.x;
    const int wid  = tid >> 5;
    const int lane = tid & 31;
    const int m0 = blockIdx.y * BM;
    const int n0 = blockIdx.x * BN;
    const uint32_t sbase = smem_to_u32(smem);

    const int wm = (wid & 3) * 32;
    const int wn = (wid >> 2) * 64;

    float acc[2][8][4];
    #pragma unroll
    for (int a = 0; a < 2; a++)
        #pragma unroll
        for (int b = 0; b < 8; b++)
            #pragma unroll
            for (int c = 0; c < 4; c++) acc[a][b][c] = 0.f;

    auto load_stage = [&](int kc, int stg) {
        const int k0 = kc * BK;
        const uint32_t b = sbase + stg * STAGE_BYTES;
        #pragma unroll
        for (int t = tid; t < 1024; t += 256) {
            int m = t >> 3, j = t & 7;
            uint32_t sw = SMEM_SWIZZLE_128B((uint32_t)(m * 128 + j * 16));
            CP_ASYNC16(b + AH_OFF + sw, (const char*)(g_Ah + (m0 + m) * D + k0) + j * 16);
            CP_ASYNC16(b + BH_OFF + sw, (const char*)(g_Bh + (n0 + m) * D + k0) + j * 16);
        }
    };

    load_stage(0, 0); CP_COMMIT();

    const int NKC = D / BK;   // 8
    for (int kc = 0; kc < NKC; kc++) {
        if (kc + 1 < NKC) { load_stage(kc + 1, (kc + 1) & 1); CP_COMMIT(); CP_WAIT(1); }
        else              { CP_WAIT(0); }
        __syncthreads();

        const uint32_t sb = sbase + (kc & 1) * STAGE_BYTES;

        #pragma unroll
        for (int ks = 0; ks < BK / 16; ks++) {
            uint32_t ah[2][4], bh[4][4];

            #pragma unroll
            for (int mt = 0; mt < 2; mt++) {
                uint32_t off = SMEM_SWIZZLE_128B(
                    (uint32_t)((wm + mt * 16 + (lane & 15)) * 128 + ks * 32 + (lane >> 4) * 16));
                ldsm_x4(ah[mt][0], ah[mt][1], ah[mt][2], ah[mt][3], sb + AH_OFF + off);
            }
            #pragma unroll
            for (int p = 0; p < 4; p++) {
                uint32_t off = SMEM_SWIZZLE_128B(
                    (uint32_t)((wn + p * 16 + ((lane >> 4) * 8) + (lane & 7)) * 128
                               + ks * 32 + ((lane >> 3) & 1) * 16));
                ldsm_x4(bh[p][0], bh[p][1], bh[p][2], bh[p][3], sb + BH_OFF + off);
            }
            #pragma unroll
            for (int mt = 0; mt < 2; mt++) {
                #pragma unroll
                for (int p = 0; p < 4; p++) {
                    mma_bf16(acc[mt][2 * p + 0], ah[mt], bh[p][0], bh[p][1]);
                    mma_bf16(acc[mt][2 * p + 1], ah[mt], bh[p][2], bh[p][3]);
                }
            }
        }
        __syncthreads();
    }

    const int g  = lane >> 2;
    const int c2 = (lane & 3) * 2;
    #pragma unroll
    for (int mt = 0; mt < 2; mt++) {
        const int row0 = m0 + wm + mt * 16 + g;
        #pragma unroll
        for (int nt = 0; nt < 8; nt++) {
            const int col = wn + nt * 8 + c2;
            __nv_bfloat162 v0 = __floats2bfloat162_rn(acc[mt][nt][0], acc[mt][nt][1]);
            __nv_bfloat162 v1 = __floats2bfloat162_rn(acc[mt][nt][2], acc[mt][nt][3]);
            *(__nv_bfloat162*)(g_Uh + (long)row0 * D + n0 + col)       = v0;
            *(__nv_bfloat162*)(g_Uh + (long)(row0 + 8) * D + n0 + col) = v1;
        }
    }
}

// ---------------------------------------------------------------------------
// Phase 2 (CSR v2): one CTA per drug row r. Uh[r] staged once in smem; each
// warp processes 4 edges CONCURRENTLY (8 batched LDG.128 -> MLP, 4 independent
// HFMA2 chains, 4 overlapping shuffle reductions). Resets g_cnt for replay.
// ---------------------------------------------------------------------------
__global__ __launch_bounds__(256) void dedicom_edge_csr_kernel(float* __restrict__ out)
{
    __shared__ uint4 su[64];
    const int r = blockIdx.x;
    int cnt = g_cnt[r];
    const int tid = threadIdx.x, wid = tid >> 5, lane = tid & 31;
    if (cnt == 0) return;
    if (cnt > CAP) cnt = CAP;

    if (tid < 64) su[tid] = ((const uint4*)(g_Uh + (long)r * D))[tid];
    __syncthreads();
    const uint4 a0 = su[lane];
    const uint4 a1 = su[lane + 32];
    const int2* bkt = g_bkt + r * CAP;

    for (int base = wid * 4; base < cnt; base += 32) {
        const int nk = min(4, cnt - base);       // warp-uniform
        int2 ce[4];
        uint4 b0[4], b1[4];
        #pragma unroll
        for (int k = 0; k < 4; k++) {
            if (k < nk) {
                ce[k] = bkt[base + k];
                const uint4* B = (const uint4*)(g_Ah + (long)ce[k].x * D);
                b0[k] = __ldg(&B[lane]);
                b1[k] = __ldg(&B[lane + 32]);
            }
        }
        #pragma unroll
        for (int k = 0; k < 4; k++) {
            if (k < nk) {
                __nv_bfloat162 zz = __floats2bfloat162_rn(0.f, 0.f);
                __nv_bfloat162 q0 = zz, q1 = zz, q2 = zz, q3 = zz;
                q0 = __hfma2(*(const __nv_bfloat162*)&a0.x, *(const __nv_bfloat162*)&b0[k].x, q0);
                q1 = __hfma2(*(const __nv_bfloat162*)&a0.y, *(const __nv_bfloat162*)&b0[k].y, q1);
                q2 = __hfma2(*(const __nv_bfloat162*)&a0.z, *(const __nv_bfloat162*)&b0[k].z, q2);
                q3 = __hfma2(*(const __nv_bfloat162*)&a0.w, *(const __nv_bfloat162*)&b0[k].w, q3);
                q0 = __hfma2(*(const __nv_bfloat162*)&a1.x, *(const __nv_bfloat162*)&b1[k].x, q0);
                q1 = __hfma2(*(const __nv_bfloat162*)&a1.y, *(const __nv_bfloat162*)&b1[k].y, q1);
                q2 = __hfma2(*(const __nv_bfloat162*)&a1.z, *(const __nv_bfloat162*)&b1[k].z, q2);
                q3 = __hfma2(*(const __nv_bfloat162*)&a1.w, *(const __nv_bfloat162*)&b1[k].w, q3);
                float2 f0 = __bfloat1622float2(q0);
                float2 f1 = __bfloat1622float2(q1);
                float2 f2 = __bfloat1622float2(q2);
                float2 f3 = __bfloat1622float2(q3);
                float acc = ((f0.x + f0.y) + (f1.x + f1.y)) + ((f2.x + f2.y) + (f3.x + f3.y));
                #pragma unroll
                for (int o = 16; o; o >>= 1) acc += __shfl_xor_sync(0xffffffffu, acc, o);
                if (lane == 0) out[ce[k].y] = 1.f / (1.f + __expf(-acc));
            }
        }
    }

    if (tid == 0) g_cnt[r] = 0;    // restore for next graph replay
}

// ---------------------------------------------------------------------------
// Launch
// ---------------------------------------------------------------------------
extern "C" void kernel_launch(void* const* d_in, const int* in_sizes, int n_in,
                              void* d_out, int out_size)
{
    const float* z     = (const float*)d_in[0];   // [4096, 512]
    const float* W     = (const float*)d_in[1];   // [512, 512]
    const float* ldiag = (const float*)d_in[2];   // [10, 512]
    const int*   edges = (const int*)d_in[3];     // [2, n_edges] int32
    const int*   idxp  = (const int*)d_in[4];     // scalar

    const int n_drugs = in_sizes[0] / D;
    const int n_edges = in_sizes[3] / 2;

    static int smem_set = 0;
    if (!smem_set) {
        cudaFuncSetAttribute(dedicom_mma_kernel,
                             cudaFuncAttributeMaxDynamicSharedMemorySize, SM_GEMM);
        smem_set = 1;
    }

    prep_a_kernel<<<(n_drugs * D / 4 + 255) / 256, 256>>>(z, ldiag, idxp);
    prep_w_kernel<<<dim3(D / 32, D / 32), dim3(32, 8)>>>(W);
    scatter_kernel<<<(n_edges + 255) / 256, 256>>>(edges, n_edges);

    dim3 gm(D / BN, n_drugs / BM);
    dedicom_mma_kernel<<<gm, 256, SM_GEMM>>>();

    dedicom_edge_csr_kernel<<<n_drugs, 256>>>((float*)d_out);
}

// round 12
// speedup vs baseline: 1.4062x; 1.4062x over previous
#include <cuda_runtime.h>
#include <cuda_bf16.h>
#include <cstdint>

#define D 512
#define NDRUGS 4096
#define BM 64
#define BN 128
#define BK 64

// ---------------- device scratch (allocation-free) ----------------
__device__ __align__(16) __nv_bfloat16  g_Uh[NDRUGS * D];    // 4 MB (U = (z*d)@W, bf16)
__device__ __align__(16) __nv_bfloat16  g_Ah[NDRUGS * D];    // 4 MB (bf16 of z*d)
__device__ __align__(16) __nv_bfloat16  g_Bh[D * D];         // 512 KB (W^T bf16)

// ---------------- helpers ----------------
__device__ __forceinline__ uint32_t smem_to_u32(const void* p) {
    uint32_t a;
    asm("{ .reg .u64 t; cvta.to.shared.u64 t, %1; cvt.u32.u64 %0, t; }" : "=r"(a) : "l"(p));
    return a;
}
#define SMEM_SWIZZLE_128B(o) ((o) ^ (((o) >> 3) & 0x70))

#define CP_ASYNC16(dst, src) \
    asm volatile("cp.async.cg.shared.global [%0], [%1], 16;" :: "r"(dst), "l"(src))
#define CP_COMMIT() asm volatile("cp.async.commit_group;" ::: "memory")
#define CP_WAIT(n)  asm volatile("cp.async.wait_group %0;" :: "n"(n) : "memory")

__device__ __forceinline__ void ldsm_x4(uint32_t& r0, uint32_t& r1, uint32_t& r2, uint32_t& r3,
                                        uint32_t addr) {
    asm volatile("ldmatrix.sync.aligned.m8n8.x4.shared.b16 {%0,%1,%2,%3}, [%4];"
                 : "=r"(r0), "=r"(r1), "=r"(r2), "=r"(r3) : "r"(addr));
}
__device__ __forceinline__ void mma_bf16(float* c, const uint32_t* a, uint32_t b0, uint32_t b1) {
    asm volatile("mma.sync.aligned.m16n8k16.row.col.f32.bf16.bf16.f32 "
                 "{%0,%1,%2,%3}, {%4,%5,%6,%7}, {%8,%9}, {%0,%1,%2,%3};"
                 : "+f"(c[0]), "+f"(c[1]), "+f"(c[2]), "+f"(c[3])
                 : "r"(a[0]), "r"(a[1]), "r"(a[2]), "r"(a[3]), "r"(b0), "r"(b1));
}

// GEMM SMEM: 3 stages x (A 8K | B 16K) = 72 KB
#define STAGE_BYTES 24576
#define A_OFF 0
#define B_OFF 8192
#define SM_GEMM (3 * STAGE_BYTES)

// ---------------------------------------------------------------------------
// Prep A: Ah = bf16(z[m,k] * d[k])
// ---------------------------------------------------------------------------
__global__ __launch_bounds__(256) void prep_a_kernel(
    const float* __restrict__ z, const float* __restrict__ ldiag, const int* __restrict__ idxp)
{
    const float* dp = ldiag + idxp[0] * D;
    int i = blockIdx.x * 256 + threadIdx.x;
    int k4 = (i & (D / 4 - 1)) << 2;
    float4 v = ((const float4*)z)[i];
    v.x *= dp[k4 + 0]; v.y *= dp[k4 + 1]; v.z *= dp[k4 + 2]; v.w *= dp[k4 + 3];

    __nv_bfloat162 h01 = __floats2bfloat162_rn(v.x, v.y);
    __nv_bfloat162 h23 = __floats2bfloat162_rn(v.z, v.w);
    uint2 hp; hp.x = *(uint32_t*)&h01; hp.y = *(uint32_t*)&h23;
    ((uint2*)g_Ah)[i] = hp;
}

// ---------------------------------------------------------------------------
// Prep W: Bh[n,k] = bf16(W[k,n])
// ---------------------------------------------------------------------------
__global__ __launch_bounds__(256) void prep_w_kernel(const float* __restrict__ W)
{
    __shared__ float t[32][33];
    int tx = threadIdx.x, ty = threadIdx.y;
    int x0 = blockIdx.x * 32, y0 = blockIdx.y * 32;
    #pragma unroll
    for (int r = 0; r < 4; r++)
        t[ty + r * 8][tx] = W[(y0 + ty + r * 8) * D + x0 + tx];
    __syncthreads();
    #pragma unroll
    for (int r = 0; r < 4; r++) {
        int n = x0 + ty + r * 8;
        int k = y0 + tx;
        g_Bh[n * D + k] = __float2bfloat16(t[tx][ty + r * 8]);
    }
}

// ---------------------------------------------------------------------------
// bf16 GEMM via mma.sync: Uh = bf16( Ah @ Wh )
// grid (D/BN=4, NDRUGS/BM=64) = 256 CTAs, 256 threads, 3-stage cp.async
// warp layout: 4m x 2n, warp tile 16 x 64
// ---------------------------------------------------------------------------
__global__ __launch_bounds__(256, 2) void dedicom_mma_kernel()
{
    extern __shared__ char smem[];
    const int tid  = threadIdx.x;
    const int wid  = tid >> 5;
    const int lane = tid & 31;
    const int m0 = blockIdx.y * BM;
    const int n0 = blockIdx.x * BN;
    const uint32_t sbase = smem_to_u32(smem);

    const int wm = (wid & 3) * 16;       // 4 m-warps x 16 rows
    const int wn = (wid >> 2) * 64;      // 2 n-warps x 64 cols

    float acc[8][4];
    #pragma unroll
    for (int b = 0; b < 8; b++)
        #pragma unroll
        for (int c = 0; c < 4; c++) acc[b][c] = 0.f;

    // stage loader: A 64x128B (512 uint4) + B 128x128B (1024 uint4) = 6/thread
    auto load_stage = [&](int kc, int stg) {
        const int k0 = kc * BK;
        const uint32_t sb = sbase + stg * STAGE_BYTES;
        #pragma unroll
        for (int t = tid; t < 512; t += 256) {
            int m = t >> 3, j = t & 7;
            uint32_t sw = SMEM_SWIZZLE_128B((uint32_t)(m * 128 + j * 16));
            CP_ASYNC16(sb + A_OFF + sw, (const char*)(g_Ah + (m0 + m) * D + k0) + j * 16);
        }
        #pragma unroll
        for (int t = tid; t < 1024; t += 256) {
            int n = t >> 3, j = t & 7;
            uint32_t sw = SMEM_SWIZZLE_128B((uint32_t)(n * 128 + j * 16));
            CP_ASYNC16(sb + B_OFF + sw, (const char*)(g_Bh + (n0 + n) * D + k0) + j * 16);
        }
    };

    const int NKC = D / BK;   // 8
    load_stage(0, 0); CP_COMMIT();
    load_stage(1, 1); CP_COMMIT();

    for (int kc = 0; kc < NKC; kc++) {
        CP_WAIT(1);                       // stage kc resident
        __syncthreads();                  // + all threads done with stage kc-1

        const uint32_t sb = sbase + (kc % 3) * STAGE_BYTES;

        #pragma unroll
        for (int ks = 0; ks < BK / 16; ks++) {
            uint32_t a[4], bh[4][4];
            {
                uint32_t off = SMEM_SWIZZLE_128B(
                    (uint32_t)((wm + (lane & 15)) * 128 + ks * 32 + (lane >> 4) * 16));
                ldsm_x4(a[0], a[1], a[2], a[3], sb + A_OFF + off);
            }
            #pragma unroll
            for (int p = 0; p < 4; p++) {
                uint32_t off = SMEM_SWIZZLE_128B(
                    (uint32_t)((wn + p * 16 + ((lane >> 4) * 8) + (lane & 7)) * 128
                               + ks * 32 + ((lane >> 3) & 1) * 16));
                ldsm_x4(bh[p][0], bh[p][1], bh[p][2], bh[p][3], sb + B_OFF + off);
            }
            #pragma unroll
            for (int p = 0; p < 4; p++) {
                mma_bf16(acc[2 * p + 0], a, bh[p][0], bh[p][1]);
                mma_bf16(acc[2 * p + 1], a, bh[p][2], bh[p][3]);
            }
        }

        if (kc + 2 < NKC) { load_stage(kc + 2, (kc + 2) % 3); CP_COMMIT(); }
    }

    // epilogue: write Uh as bf16 pairs
    const int g  = lane >> 2;
    const int c2 = (lane & 3) * 2;
    const int row0 = m0 + wm + g;
    #pragma unroll
    for (int nt = 0; nt < 8; nt++) {
        const int col = wn + nt * 8 + c2;
        __nv_bfloat162 v0 = __floats2bfloat162_rn(acc[nt][0], acc[nt][1]);
        __nv_bfloat162 v1 = __floats2bfloat162_rn(acc[nt][2], acc[nt][3]);
        *(__nv_bfloat162*)(g_Uh + (long)row0 * D + n0 + col)       = v0;
        *(__nv_bfloat162*)(g_Uh + (long)(row0 + 8) * D + n0 + col) = v1;
    }
}

// ---------------------------------------------------------------------------
// Phase 2 (flat, proven 23.5 us @ LTS cap): one warp per edge.
// ---------------------------------------------------------------------------
__global__ __launch_bounds__(256) void dedicom_edge_kernel(
    const int* __restrict__ edges,
    float* __restrict__ out,
    int n_edges)
{
    const int w    = (blockIdx.x * blockDim.x + threadIdx.x) >> 5;
    const int lane = threadIdx.x & 31;
    if (w >= n_edges) return;

    const int r = edges[w];
    const int c = edges[n_edges + w];

    const uint4* vr = (const uint4*)(g_Uh + (long)r * D);
    const uint4* zc = (const uint4*)(g_Ah + (long)c * D);

    __nv_bfloat162 z2 = __floats2bfloat162_rn(0.f, 0.f);
    __nv_bfloat162 q0 = z2, q1 = z2, q2 = z2, q3 = z2;

    #pragma unroll
    for (int i = 0; i < 2; i++) {
        uint4 a = __ldg(&vr[lane + i * 32]);
        uint4 b = __ldg(&zc[lane + i * 32]);
        q0 = __hfma2(*(const __nv_bfloat162*)&a.x, *(const __nv_bfloat162*)&b.x, q0);
        q1 = __hfma2(*(const __nv_bfloat162*)&a.y, *(const __nv_bfloat162*)&b.y, q1);
        q2 = __hfma2(*(const __nv_bfloat162*)&a.z, *(const __nv_bfloat162*)&b.z, q2);
        q3 = __hfma2(*(const __nv_bfloat162*)&a.w, *(const __nv_bfloat162*)&b.w, q3);
    }

    float2 f0 = __bfloat1622float2(q0);
    float2 f1 = __bfloat1622float2(q1);
    float2 f2 = __bfloat1622float2(q2);
    float2 f3 = __bfloat1622float2(q3);
    float acc = ((f0.x + f0.y) + (f1.x + f1.y)) + ((f2.x + f2.y) + (f3.x + f3.y));

    #pragma unroll
    for (int o = 16; o; o >>= 1) acc += __shfl_xor_sync(0xffffffffu, acc, o);

    if (lane == 0) out[w] = 1.f / (1.f + __expf(-acc));
}

// ---------------------------------------------------------------------------
// Launch
// ---------------------------------------------------------------------------
extern "C" void kernel_launch(void* const* d_in, const int* in_sizes, int n_in,
                              void* d_out, int out_size)
{
    const float* z     = (const float*)d_in[0];   // [4096, 512]
    const float* W     = (const float*)d_in[1];   // [512, 512]
    const float* ldiag = (const float*)d_in[2];   // [10, 512]
    const int*   edges = (const int*)d_in[3];     // [2, n_edges] int32
    const int*   idxp  = (const int*)d_in[4];     // scalar

    const int n_drugs = in_sizes[0] / D;
    const int n_edges = in_sizes[3] / 2;

    static int smem_set = 0;
    if (!smem_set) {
        cudaFuncSetAttribute(dedicom_mma_kernel,
                             cudaFuncAttributeMaxDynamicSharedMemorySize, SM_GEMM);
        smem_set = 1;
    }

    prep_a_kernel<<<(n_drugs * D / 4 + 255) / 256, 256>>>(z, ldiag, idxp);
    prep_w_kernel<<<dim3(D / 32, D / 32), dim3(32, 8)>>>(W);

    dim3 gm(D / BN, n_drugs / BM);
    dedicom_mma_kernel<<<gm, 256, SM_GEMM>>>();

    int blocks = (n_edges + 7) / 8;
    dedicom_edge_kernel<<<blocks, 256>>>(edges, (float*)d_out, n_edges);
}